// round 10
// baseline (speedup 1.0000x reference)
#include <cuda_runtime.h>

// EffectiveProbability: post = normalize(p * (CM @ c)) per pixel.
// Input row-normalizations cancel against the output normalization -> skipped.
//
// prior/current [8,21,512,512] f32, cm [21,21] f32, out [B*H*W,21] f32.
//
// R10: R9 (86.5us: constant-bank CM via LDCU, 1 px/thread, all 42 gmem loads
// front-batched, smem-staged coalesced flush) + ONE change: drop the post[21]
// register array by deferring normalization to the flush (s_out holds
// unnormalized t, s_inv holds 1/acc). pv[] stays front-batched (R2 proved the
// deferral is only safe with no in-loop DRAM loads). Fewer regs -> 5 blocks/SM
// (launch_bounds 256,5) -> more warps covering DRAM latency.

#define NCLS 21
#define HWSHIFT 18              // H*W = 512*512 = 2^18
#define HWSZ (1 << HWSHIFT)
#define BLOCK 256

__constant__ float c_cm[NCLS * NCLS];

__global__ __launch_bounds__(BLOCK, 5)
void eff_prob_kernel(const float* __restrict__ prior,
                     const float* __restrict__ current,
                     float* __restrict__ out,
                     int npix)
{
    __shared__ float s_out[BLOCK * NCLS];
    __shared__ float s_inv[BLOCK];

    const int tid = threadIdx.x;
    const int n = blockIdx.x * BLOCK + tid;
    if (n < npix) {
        const int b  = n >> HWSHIFT;
        const int hw = n & (HWSZ - 1);
        const size_t base = ((size_t)b * NCLS << HWSHIFT) + hw;
        const float* __restrict__ cp = current + base;
        const float* __restrict__ pp = prior + base;

        // Front-batched fully-coalesced loads: maximum MLP, no in-loop DRAM.
        float cv[NCLS];
        #pragma unroll
        for (int j = 0; j < NCLS; j++) cv[j] = cp[(size_t)j << HWSHIFT];
        float pv[NCLS];
        #pragma unroll
        for (int j = 0; j < NCLS; j++) pv[j] = pp[(size_t)j << HWSHIFT];

        float acc = 0.0f;
        float* so = s_out + tid * NCLS;   // stride 21: gcd(21,32)=1, conflict-free
        #pragma unroll
        for (int i = 0; i < NCLS; i++) {
            float s = 0.0f;
            #pragma unroll
            for (int j = 0; j < NCLS; j++)
                s = fmaf(c_cm[i * NCLS + j], cv[j], s);   // LDCU (uniform port) + FFMA
            const float t = pv[i] * s;
            so[i] = t;                    // unnormalized; scaled in the flush
            acc += t;
        }
        s_inv[tid] = 1.0f / acc;
    }
    __syncthreads();

    // Flush block tile [BLOCK, 21] linearly -> fully coalesced 128B stores.
    // Incremental k/21 tracking: step +256 = +12*21+4 (no divide in loop).
    const long out_base = (long)blockIdx.x * BLOCK * NCLS;
    const int  valid    = min(BLOCK, npix - blockIdx.x * BLOCK);
    const int  count    = valid * NCLS;
    int pix = tid / NCLS;                 // one-time small division
    int c   = tid - pix * NCLS;
    for (int k = tid; k < count; k += BLOCK) {
        out[out_base + k] = s_out[k] * s_inv[pix];
        c += 4;                           // 256 mod 21 = 4
        pix += 12;                        // 256 / 21 = 12
        if (c >= NCLS) { c -= NCLS; pix++; }
    }
}

extern "C" void kernel_launch(void* const* d_in, const int* in_sizes, int n_in,
                              void* d_out, int out_size)
{
    const float* prior   = (const float*)d_in[0];
    const float* current = (const float*)d_in[1];
    const float* cm      = (const float*)d_in[2];
    float*       out     = (float*)d_out;

    // D2D copy into the constant bank; async -> graph-capturable memcpy node.
    cudaMemcpyToSymbolAsync(c_cm, cm, NCLS * NCLS * sizeof(float), 0,
                            cudaMemcpyDeviceToDevice, 0);

    const int npix = in_sizes[0] / NCLS;   // B*H*W
    const int grid = (npix + BLOCK - 1) / BLOCK;
    eff_prob_kernel<<<grid, BLOCK>>>(prior, current, out, npix);
}

// round 11
// speedup vs baseline: 1.0483x; 1.0483x over previous
#include <cuda_runtime.h>

// EffectiveProbability: post = normalize(p * (CM @ c)) per pixel.
// Input row-normalizations cancel against the output normalization -> skipped.
//
// prior/current [8,21,512,512] f32, cm [21,21] f32, out [B*H*W,21] f32.
//
// R11: R9 (best: 86.5us; constant-bank CM via uniform-port LDCU, 1 px/thread,
// all 42 gmem loads front-batched, normalize in registers, smem-staged
// coalesced flush) + two low-risk epilogue/memory-path changes:
//  - float4-vectorized flush (LDS.128 + STG.128): 42 -> ~11 issues/thread,
//    values already normalized so zero per-element ALU (R10's mistake).
//  - streaming cache hints: __ldcs on the 528MB single-touch input stream,
//    __stcs on the output stream (evict-first, keeps L2 clean).

#define NCLS 21
#define HWSHIFT 18              // H*W = 512*512 = 2^18
#define HWSZ (1 << HWSHIFT)
#define BLOCK 256

__constant__ float c_cm[NCLS * NCLS];

__global__ __launch_bounds__(BLOCK)
void eff_prob_kernel(const float* __restrict__ prior,
                     const float* __restrict__ current,
                     float* __restrict__ out,
                     int npix)
{
    __shared__ float s_out[BLOCK * NCLS];    // 21504 B, 16B-divisible

    const int tid = threadIdx.x;
    const int n = blockIdx.x * BLOCK + tid;
    if (n < npix) {
        const int b  = n >> HWSHIFT;
        const int hw = n & (HWSZ - 1);
        const size_t base = ((size_t)b * NCLS << HWSHIFT) + hw;
        const float* __restrict__ cp = current + base;
        const float* __restrict__ pp = prior + base;

        // Front-batched fully-coalesced streaming loads (single-touch data:
        // evict-first). Maximum MLP; no in-loop DRAM dependency.
        float cv[NCLS];
        #pragma unroll
        for (int j = 0; j < NCLS; j++) cv[j] = __ldcs(cp + ((size_t)j << HWSHIFT));
        float pv[NCLS];
        #pragma unroll
        for (int j = 0; j < NCLS; j++) pv[j] = __ldcs(pp + ((size_t)j << HWSHIFT));

        float post[NCLS];
        float acc = 0.0f;
        #pragma unroll
        for (int i = 0; i < NCLS; i++) {
            float s = 0.0f;
            #pragma unroll
            for (int j = 0; j < NCLS; j++)
                s = fmaf(c_cm[i * NCLS + j], cv[j], s);   // LDCU (uniform port) + FFMA
            const float t = pv[i] * s;
            post[i] = t;
            acc += t;
        }
        const float inv = 1.0f / acc;

        // Normalized values into smem staging.
        // Write stride 21 words across the warp: gcd(21,32)=1 -> conflict-free.
        #pragma unroll
        for (int i = 0; i < NCLS; i++)
            s_out[tid * NCLS + i] = post[i] * inv;
    }
    __syncthreads();

    // Vectorized flush: [BLOCK*21] floats = BLOCK*21/4 float4 groups.
    // Fully coalesced 128B LDS.128 + STG.128, streaming stores.
    const int    valid   = min(BLOCK, npix - blockIdx.x * BLOCK);
    const size_t out_off = (size_t)blockIdx.x * BLOCK * NCLS;
    if (valid == BLOCK) {
        float4*       o4 = (float4*)(out + out_off);
        const float4* s4 = (const float4*)s_out;
        #pragma unroll
        for (int k = tid; k < BLOCK * NCLS / 4; k += BLOCK)
            __stcs(o4 + k, s4[k]);
    } else {
        // Tail (never taken for npix = 2^21): scalar flush.
        const int count = valid * NCLS;
        for (int k = tid; k < count; k += BLOCK)
            __stcs(out + out_off + k, s_out[k]);
    }
}

extern "C" void kernel_launch(void* const* d_in, const int* in_sizes, int n_in,
                              void* d_out, int out_size)
{
    const float* prior   = (const float*)d_in[0];
    const float* current = (const float*)d_in[1];
    const float* cm      = (const float*)d_in[2];
    float*       out     = (float*)d_out;

    // D2D copy into the constant bank; async -> graph-capturable memcpy node.
    cudaMemcpyToSymbolAsync(c_cm, cm, NCLS * NCLS * sizeof(float), 0,
                            cudaMemcpyDeviceToDevice, 0);

    const int npix = in_sizes[0] / NCLS;   // B*H*W
    const int grid = (npix + BLOCK - 1) / BLOCK;
    eff_prob_kernel<<<grid, BLOCK>>>(prior, current, out, npix);
}